// round 4
// baseline (speedup 1.0000x reference)
#include <cuda_runtime.h>
#include <cstdint>

// out[b,n,m] = sum_e A[b,n,e]*B[b,m,e];  b=8, n=m=2048, e=1024, fp32.
// mma.sync bf16 hi/lo 3-pass (compute_103-safe; tcgen05 unavailable in this
// harness's PTX target).

static constexpr int DN = 2048, DM = 2048, DE = 1024;
static constexpr int BM = 128, BN = 128, BK = 32;   // fp32 K per chunk
static constexpr int NCHUNK = DE / BK;              // 32

static constexpr unsigned PLANE  = 128u * 128u;     // one operand tile: 128 rows x 128B (hi|lo)
static constexpr unsigned STAGE  = 2u * PLANE;      // A + B = 32 KB
static constexpr unsigned CPITCH = 132;             // fp32 pitch for C staging
static constexpr unsigned SMEM_TOTAL = 128u * CPITCH * 4u > 2u * STAGE
                                     ? 128u * CPITCH * 4u : 2u * STAGE;   // 67584

__device__ __forceinline__ unsigned smem_u32(const void* p) {
    unsigned a;
    asm("{ .reg .u64 t; cvta.to.shared.u64 t, %1; cvt.u32.u64 %0, t; }" : "=r"(a) : "l"(p));
    return a;
}

#define LDSM4(r0, r1, r2, r3, addr) \
    asm volatile("ldmatrix.sync.aligned.m8n8.x4.shared.b16 {%0,%1,%2,%3}, [%4];" \
                 : "=r"(r0), "=r"(r1), "=r"(r2), "=r"(r3) : "r"(addr))

#define MMA16816(d, a, b) \
    asm volatile("mma.sync.aligned.m16n8k16.row.col.f32.bf16.bf16.f32 " \
                 "{%0,%1,%2,%3},{%4,%5,%6,%7},{%8,%9},{%0,%1,%2,%3};" \
                 : "+f"((d)[0]), "+f"((d)[1]), "+f"((d)[2]), "+f"((d)[3]) \
                 : "r"((a)[0]), "r"((a)[1]), "r"((a)[2]), "r"((a)[3]), \
                   "r"((b)[0]), "r"((b)[1]))

// Convert 4 float4 (16 fp32) to hi/lo bf16 and store into the SW128 row.
// Row layout (128 B): bytes [0,64) = hi bf16 cols 0..31, [64,128) = lo.
// phys(row, idx16) = row*128 + 16*(idx16 ^ (row&7)), idx16 = byte/16.
__device__ __forceinline__ void cvt_sts(const float4* f, unsigned plane_base,
                                        unsigned row, unsigned half) {
    unsigned hw[8], lw[8];
#pragma unroll
    for (int i = 0; i < 4; ++i) {
        unsigned h01, h23;
        asm("cvt.rn.bf16x2.f32 %0, %1, %2;" : "=r"(h01) : "f"(f[i].y), "f"(f[i].x));
        asm("cvt.rn.bf16x2.f32 %0, %1, %2;" : "=r"(h23) : "f"(f[i].w), "f"(f[i].z));
        float l0 = f[i].x - __uint_as_float(h01 << 16);
        float l1 = f[i].y - __uint_as_float(h01 & 0xFFFF0000u);
        float l2 = f[i].z - __uint_as_float(h23 << 16);
        float l3 = f[i].w - __uint_as_float(h23 & 0xFFFF0000u);
        unsigned q01, q23;
        asm("cvt.rn.bf16x2.f32 %0, %1, %2;" : "=r"(q01) : "f"(l1), "f"(l0));
        asm("cvt.rn.bf16x2.f32 %0, %1, %2;" : "=r"(q23) : "f"(l3), "f"(l2));
        hw[2*i] = h01; hw[2*i+1] = h23; lw[2*i] = q01; lw[2*i+1] = q23;
    }
    const unsigned rbase = plane_base + row * 128u;
    const unsigned rx = row & 7u;
#pragma unroll
    for (int g = 0; g < 2; ++g) {
        unsigned ih = (2u*half + (unsigned)g) ^ rx;       // hi idx 0..3
        asm volatile("st.shared.v4.b32 [%0], {%1,%2,%3,%4};"
                     :: "r"(rbase + 16u*ih), "r"(hw[4*g]), "r"(hw[4*g+1]),
                        "r"(hw[4*g+2]), "r"(hw[4*g+3]) : "memory");
        unsigned il = (4u + 2u*half + (unsigned)g) ^ rx;  // lo idx 4..7
        asm volatile("st.shared.v4.b32 [%0], {%1,%2,%3,%4};"
                     :: "r"(rbase + 16u*il), "r"(lw[4*g]), "r"(lw[4*g+1]),
                        "r"(lw[4*g+2]), "r"(lw[4*g+3]) : "memory");
    }
}

__global__ void __launch_bounds__(256, 1)
bmm_hmma_split_kernel(const float* __restrict__ A, const float* __restrict__ B,
                      float* __restrict__ out) {
    extern __shared__ char smem[];
    const unsigned sbase = smem_u32(smem);
    const int tid = threadIdx.x, wid = tid >> 5, lane = tid & 31;
    const int bb = blockIdx.y;
    const int m0 = (blockIdx.x >> 4) * BM;   // output-row tile (mat_0 rows)
    const int n0 = (blockIdx.x & 15) * BN;   // output-col tile (mat_1 rows)

    // ---- loader mapping: each thread owns half a row's K-chunk (16 fp32) ----
    const unsigned lrow = (unsigned)(tid >> 1), lhalf = (unsigned)(tid & 1);
    const float* agp = A + ((size_t)(bb * DN + m0 + (int)lrow)) * DE + lhalf * 16;
    const float* bgp = B + ((size_t)(bb * DM + n0 + (int)lrow)) * DE + lhalf * 16;

    // ---- compute warp mapping: 2x4 warps, warp tile 64(M) x 32(N) ----
    const int wm = (wid >> 2) * 64, wn = (wid & 3) * 32;
    // ldmatrix lane geometry
    const int a_r   = lane & 15;           // A: row within m16 block
    const int a_sel = (lane >> 4) & 1;     // A: k+8 half
    const int b_r   = (lane & 7) + ((lane >> 4) << 3);  // B: row within n16 pair
    const int b_sel = (lane >> 3) & 1;     // B: k+8 half

    float acc[4][4][4];
#pragma unroll
    for (int i = 0; i < 4; ++i)
#pragma unroll
        for (int j = 0; j < 4; ++j)
#pragma unroll
            for (int c = 0; c < 4; ++c) acc[i][j][c] = 0.0f;

    // ---- prologue: chunk 0 ----
    float4 ra[4], rb[4];
#pragma unroll
    for (int g = 0; g < 4; ++g) {
        ra[g] = reinterpret_cast<const float4*>(agp)[g];
        rb[g] = reinterpret_cast<const float4*>(bgp)[g];
    }
    cvt_sts(ra, sbase,          lrow, lhalf);
    cvt_sts(rb, sbase + PLANE,  lrow, lhalf);
    __syncthreads();

    for (int kc = 0; kc < NCHUNK; ++kc) {
        // prefetch next chunk's fp32 into registers (latency hidden by MMAs)
        if (kc + 1 < NCHUNK) {
            const float* an = agp + (kc + 1) * BK;
            const float* bn = bgp + (kc + 1) * BK;
#pragma unroll
            for (int g = 0; g < 4; ++g) {
                ra[g] = reinterpret_cast<const float4*>(an)[g];
                rb[g] = reinterpret_cast<const float4*>(bn)[g];
            }
        }

        const unsigned stg = sbase + (unsigned)(kc & 1) * STAGE;
        const unsigned sA = stg, sB = stg + PLANE;

#pragma unroll
        for (int s = 0; s < 2; ++s) {
            unsigned bh[4][2], bl[4][2], af[4][4];
            // B hi + lo fragments (4 n8 blocks each)
#pragma unroll
            for (int jj = 0; jj < 2; ++jj) {
                const unsigned row = (unsigned)(wn + 16 * jj + b_r);
                const unsigned rb128 = sB + row * 128u;
                const unsigned rx = row & 7u;
                LDSM4(bh[2*jj][0], bh[2*jj][1], bh[2*jj+1][0], bh[2*jj+1][1],
                      rb128 + 16u * ((unsigned)(2*s + b_sel) ^ rx));
                LDSM4(bl[2*jj][0], bl[2*jj][1], bl[2*jj+1][0], bl[2*jj+1][1],
                      rb128 + 16u * ((unsigned)(4 + 2*s + b_sel) ^ rx));
            }
            // A hi fragments
#pragma unroll
            for (int i = 0; i < 4; ++i) {
                const unsigned row = (unsigned)(wm + 16 * i + a_r);
                LDSM4(af[i][0], af[i][1], af[i][2], af[i][3],
                      sA + row * 128u + 16u * ((unsigned)(2*s + a_sel) ^ (row & 7u)));
            }
#pragma unroll
            for (int i = 0; i < 4; ++i)
#pragma unroll
                for (int j = 0; j < 4; ++j) {
                    MMA16816(acc[i][j], af[i], bh[j]);   // hi*hi
                    MMA16816(acc[i][j], af[i], bl[j]);   // hi*lo
                }
            // A lo fragments (reuse regs)
#pragma unroll
            for (int i = 0; i < 4; ++i) {
                const unsigned row = (unsigned)(wm + 16 * i + a_r);
                LDSM4(af[i][0], af[i][1], af[i][2], af[i][3],
                      sA + row * 128u + 16u * ((unsigned)(4 + 2*s + a_sel) ^ (row & 7u)));
            }
#pragma unroll
            for (int i = 0; i < 4; ++i)
#pragma unroll
                for (int j = 0; j < 4; ++j)
                    MMA16816(acc[i][j], af[i], bh[j]);   // lo*hi
        }

        if (kc + 1 < NCHUNK) {
            const unsigned nstg = sbase + (unsigned)((kc + 1) & 1) * STAGE;
            cvt_sts(ra, nstg,         lrow, lhalf);
            cvt_sts(rb, nstg + PLANE, lrow, lhalf);
        }
        __syncthreads();
    }

    // ---- epilogue: stage C in smem (pitch 132), then coalesced stores ----
    {
        const int r0 = wm + (lane >> 2);
        const int c0 = wn + 2 * (lane & 3);
#pragma unroll
        for (int i = 0; i < 4; ++i)
#pragma unroll
            for (int j = 0; j < 4; ++j) {
                const unsigned e0 = sbase + ((unsigned)(r0 + 16*i) * CPITCH
                                             + (unsigned)(c0 + 8*j)) * 4u;
                asm volatile("st.shared.v2.f32 [%0], {%1,%2};"
                             :: "r"(e0), "f"(acc[i][j][0]), "f"(acc[i][j][1]) : "memory");
                const unsigned e1 = e0 + 8u * CPITCH * 4u;
                asm volatile("st.shared.v2.f32 [%0], {%1,%2};"
                             :: "r"(e1), "f"(acc[i][j][2]), "f"(acc[i][j][3]) : "memory");
            }
    }
    __syncthreads();
    {
        const int r = tid >> 1, h = tid & 1;
        float* orow = out + ((size_t)(bb * DN) + m0 + r) * DM + n0 + h * 64;
        const unsigned srow = sbase + ((unsigned)r * CPITCH + (unsigned)h * 64u) * 4u;
#pragma unroll
        for (int g = 0; g < 16; ++g) {
            float4 v;
            asm volatile("ld.shared.v4.f32 {%0,%1,%2,%3}, [%4];"
                         : "=f"(v.x), "=f"(v.y), "=f"(v.z), "=f"(v.w)
                         : "r"(srow + (unsigned)g * 16u));
            reinterpret_cast<float4*>(orow)[g] = v;
        }
    }
}

extern "C" void kernel_launch(void* const* d_in, const int* in_sizes, int n_in,
                              void* d_out, int out_size) {
    const float* A = (const float*)d_in[0];
    const float* B = (const float*)d_in[1];
    float* out = (float*)d_out;
    cudaFuncSetAttribute(bmm_hmma_split_kernel,
                         cudaFuncAttributeMaxDynamicSharedMemorySize, (int)SMEM_TOTAL);
    dim3 grid(256, 8);   // 16x16 tiles per batch, 8 batches
    bmm_hmma_split_kernel<<<grid, 256, SMEM_TOTAL>>>(A, B, out);
}

// round 5
// speedup vs baseline: 1.2880x; 1.2880x over previous
#include <cuda_runtime.h>
#include <cstdint>

// out[b,n,m] = sum_e A[b,n,e]*B[b,m,e]; b=8, n=m=2048, e=1024, fp32.
// Pass 1: fp32 -> packed (hi|lo) bf16 split rows in __device__ scratch.
// Pass 2: HMMA bf16 3-pass GEMM, cp.async operand feed, warp tile 64x64.

static constexpr int DN = 2048, DM = 2048, DE = 1024;
static constexpr int BK = 32, NCHUNK = DE / BK;          // 32 fp32 per chunk
static constexpr int BM = 128, BN = 256;                 // CTA tile

// scratch: [mat(2)][b(8)][kc(32)][row(2048)][128B]  = 128 MB
__device__ __align__(128) uint4 g_split[2u * 8u * 32u * 2048u * 8u];

static constexpr unsigned A_PLANE = 128u * 128u;          // 16 KB
static constexpr unsigned B_PLANE = 256u * 128u;          // 32 KB
static constexpr unsigned STAGE   = A_PLANE + B_PLANE;    // 48 KB
static constexpr unsigned SMEM_TOTAL = 2u * STAGE;        // 96 KB

__device__ __forceinline__ unsigned smem_u32(const void* p) {
    unsigned a;
    asm("{ .reg .u64 t; cvta.to.shared.u64 t, %1; cvt.u32.u64 %0, t; }" : "=r"(a) : "l"(p));
    return a;
}

#define LDSM4(r0, r1, r2, r3, addr) \
    asm volatile("ldmatrix.sync.aligned.m8n8.x4.shared.b16 {%0,%1,%2,%3}, [%4];" \
                 : "=r"(r0), "=r"(r1), "=r"(r2), "=r"(r3) : "r"(addr))

#define MMA16816(d, a, b) \
    asm volatile("mma.sync.aligned.m16n8k16.row.col.f32.bf16.bf16.f32 " \
                 "{%0,%1,%2,%3},{%4,%5,%6,%7},{%8,%9},{%0,%1,%2,%3};" \
                 : "+f"((d)[0]), "+f"((d)[1]), "+f"((d)[2]), "+f"((d)[3]) \
                 : "r"((a)[0]), "r"((a)[1]), "r"((a)[2]), "r"((a)[3]), \
                   "r"((b)[0]), "r"((b)[1]))

#define CPASYNC16(dst, src) \
    asm volatile("cp.async.cg.shared.global [%0], [%1], 16;" :: "r"(dst), "l"(src))

// ---------------------------------------------------------------------------
// Pass 1: convert one 32-elem K-chunk of one row -> 128B (hi 64B | lo 64B).
// gid bits: [mat:1][b:3][kc:5][r:11]
// ---------------------------------------------------------------------------
__global__ void __launch_bounds__(256)
split_prepass(const float* __restrict__ A, const float* __restrict__ B) {
    const unsigned gid = blockIdx.x * 256u + threadIdx.x;
    const unsigned r   = gid & 2047u;
    const unsigned kc  = (gid >> 11) & 31u;
    const unsigned b   = (gid >> 16) & 7u;
    const unsigned mat = (gid >> 19) & 1u;

    const float* src = (mat ? B : A) + ((size_t)(b * 2048u + r)) * 1024u + kc * 32u;
    unsigned hw[16], lw[16];
#pragma unroll
    for (int i = 0; i < 8; ++i) {
        float4 f = reinterpret_cast<const float4*>(src)[i];
        unsigned h01, h23;
        asm("cvt.rn.bf16x2.f32 %0, %1, %2;" : "=r"(h01) : "f"(f.y), "f"(f.x));
        asm("cvt.rn.bf16x2.f32 %0, %1, %2;" : "=r"(h23) : "f"(f.w), "f"(f.z));
        float l0 = f.x - __uint_as_float(h01 << 16);
        float l1 = f.y - __uint_as_float(h01 & 0xFFFF0000u);
        float l2 = f.z - __uint_as_float(h23 << 16);
        float l3 = f.w - __uint_as_float(h23 & 0xFFFF0000u);
        unsigned q01, q23;
        asm("cvt.rn.bf16x2.f32 %0, %1, %2;" : "=r"(q01) : "f"(l1), "f"(l0));
        asm("cvt.rn.bf16x2.f32 %0, %1, %2;" : "=r"(q23) : "f"(l3), "f"(l2));
        hw[2*i] = h01; hw[2*i+1] = h23; lw[2*i] = q01; lw[2*i+1] = q23;
    }
    uint4* dst = g_split + (((size_t)(mat * 8u + b) * 32u + kc) * 2048u + r) * 8u;
#pragma unroll
    for (int q = 0; q < 4; ++q)
        dst[q] = make_uint4(hw[4*q], hw[4*q+1], hw[4*q+2], hw[4*q+3]);
#pragma unroll
    for (int q = 0; q < 4; ++q)
        dst[4 + q] = make_uint4(lw[4*q], lw[4*q+1], lw[4*q+2], lw[4*q+3]);
}

// ---------------------------------------------------------------------------
// Pass 2 helpers
// ---------------------------------------------------------------------------
__device__ __forceinline__ void issue_stage(const uint4* __restrict__ aT,
                                            const uint4* __restrict__ bT,
                                            unsigned stg, unsigned tid) {
#pragma unroll
    for (int g = 0; g < 4; ++g) {                  // A: 1024 x 16B units
        unsigned u = tid + (unsigned)g * 256u;
        unsigned row = u >> 3, idx = u & 7u;
        unsigned dst = stg + row * 128u + 16u * (idx ^ (row & 7u));
        CPASYNC16(dst, (const void*)(aT + u));
    }
#pragma unroll
    for (int g = 0; g < 8; ++g) {                  // B: 2048 x 16B units
        unsigned u = tid + (unsigned)g * 256u;
        unsigned row = u >> 3, idx = u & 7u;
        unsigned dst = stg + A_PLANE + row * 128u + 16u * (idx ^ (row & 7u));
        CPASYNC16(dst, (const void*)(bT + u));
    }
}

__global__ void __launch_bounds__(256, 1)
bmm_hmma_cpasync_kernel(float* __restrict__ out) {
    extern __shared__ char smem[];
    const unsigned sbase = smem_u32(smem);
    const unsigned tid = threadIdx.x;
    const int wid = (int)(tid >> 5), lane = (int)(tid & 31);
    const int bb = blockIdx.y;
    const int m0 = (int)(blockIdx.x >> 3) * BM;    // 16 m-tiles
    const int n0 = (int)(blockIdx.x & 7) * BN;     // 8 n-tiles

    // scratch tile bases (uint4 units); A = mat0, B = mat1
    const uint4* aBase = g_split + ((size_t)bb * 32u * 2048u + (size_t)m0) * 8u;
    const uint4* bBase = g_split + (((size_t)(8 + bb)) * 32u * 2048u + (size_t)n0) * 8u;
    const size_t CHUNK_STRIDE = 2048u * 8u;        // uint4 per kc step

    // warp grid 2(M) x 4(N); warp tile 64 x 64
    const int wm = (wid >> 2) * 64, wn = (wid & 3) * 64;
    const int a_r   = lane & 15;
    const int a_sel = (lane >> 4) & 1;
    const int b_r   = (lane & 7) + ((lane >> 4) << 3);
    const int b_sel = (lane >> 3) & 1;

    float acc[4][8][4];
#pragma unroll
    for (int i = 0; i < 4; ++i)
#pragma unroll
        for (int j = 0; j < 8; ++j)
#pragma unroll
            for (int c = 0; c < 4; ++c) acc[i][j][c] = 0.0f;

    issue_stage(aBase, bBase, sbase, tid);
    asm volatile("cp.async.commit_group;" ::: "memory");

    for (int kc = 0; kc < NCHUNK; ++kc) {
        if (kc + 1 < NCHUNK) {
            issue_stage(aBase + (size_t)(kc + 1) * CHUNK_STRIDE,
                        bBase + (size_t)(kc + 1) * CHUNK_STRIDE,
                        sbase + (unsigned)((kc + 1) & 1) * STAGE, tid);
            asm volatile("cp.async.commit_group;" ::: "memory");
            asm volatile("cp.async.wait_group 1;" ::: "memory");
        } else {
            asm volatile("cp.async.wait_group 0;" ::: "memory");
        }
        __syncthreads();

        const unsigned stg = sbase + (unsigned)(kc & 1) * STAGE;
        const unsigned sA = stg, sB = stg + A_PLANE;

#pragma unroll
        for (int s = 0; s < 2; ++s) {
            unsigned af[4][4], bh[8][2], bl[8][2];
            // B hi fragments (8 n8 blocks)
#pragma unroll
            for (int jj = 0; jj < 4; ++jj) {
                const unsigned row = (unsigned)(wn + 16 * jj + b_r);
                LDSM4(bh[2*jj][0], bh[2*jj][1], bh[2*jj+1][0], bh[2*jj+1][1],
                      sB + row * 128u + 16u * ((unsigned)(2*s + b_sel) ^ (row & 7u)));
            }
            // A hi fragments
#pragma unroll
            for (int i = 0; i < 4; ++i) {
                const unsigned row = (unsigned)(wm + 16 * i + a_r);
                LDSM4(af[i][0], af[i][1], af[i][2], af[i][3],
                      sA + row * 128u + 16u * ((unsigned)(2*s + a_sel) ^ (row & 7u)));
            }
#pragma unroll
            for (int i = 0; i < 4; ++i)
#pragma unroll
                for (int j = 0; j < 8; ++j)
                    MMA16816(acc[i][j], af[i], bh[j]);          // hi*hi
            // B lo fragments
#pragma unroll
            for (int jj = 0; jj < 4; ++jj) {
                const unsigned row = (unsigned)(wn + 16 * jj + b_r);
                LDSM4(bl[2*jj][0], bl[2*jj][1], bl[2*jj+1][0], bl[2*jj+1][1],
                      sB + row * 128u + 16u * ((unsigned)(4 + 2*s + b_sel) ^ (row & 7u)));
            }
#pragma unroll
            for (int i = 0; i < 4; ++i)
#pragma unroll
                for (int j = 0; j < 8; ++j)
                    MMA16816(acc[i][j], af[i], bl[j]);          // hi*lo
            // A lo fragments (overwrite af)
#pragma unroll
            for (int i = 0; i < 4; ++i) {
                const unsigned row = (unsigned)(wm + 16 * i + a_r);
                LDSM4(af[i][0], af[i][1], af[i][2], af[i][3],
                      sA + row * 128u + 16u * ((unsigned)(4 + 2*s + a_sel) ^ (row & 7u)));
            }
#pragma unroll
            for (int i = 0; i < 4; ++i)
#pragma unroll
                for (int j = 0; j < 8; ++j)
                    MMA16816(acc[i][j], af[i], bh[j]);          // lo*hi
        }
        __syncthreads();
    }

    // epilogue: direct global stores (float2 per fragment half)
    {
        const int r0 = wm + (lane >> 2);
        const int c0 = wn + 2 * (lane & 3);
        float* obase = out + ((size_t)(bb * DN) + (size_t)m0) * DM + n0;
#pragma unroll
        for (int i = 0; i < 4; ++i)
#pragma unroll
            for (int j = 0; j < 8; ++j) {
                float* p0 = obase + (size_t)(r0 + 16*i) * DM + (c0 + 8*j);
                reinterpret_cast<float2*>(p0)[0] = make_float2(acc[i][j][0], acc[i][j][1]);
                float* p1 = p0 + 8 * DM;
                reinterpret_cast<float2*>(p1)[0] = make_float2(acc[i][j][2], acc[i][j][3]);
            }
    }
}

extern "C" void kernel_launch(void* const* d_in, const int* in_sizes, int n_in,
                              void* d_out, int out_size) {
    const float* A = (const float*)d_in[0];
    const float* B = (const float*)d_in[1];
    float* out = (float*)d_out;

    split_prepass<<<4096, 256>>>(A, B);

    cudaFuncSetAttribute(bmm_hmma_cpasync_kernel,
                         cudaFuncAttributeMaxDynamicSharedMemorySize, (int)SMEM_TOTAL);
    dim3 grid(128, 8);   // 16 x 8 tiles per batch, 8 batches
    bmm_hmma_cpasync_kernel<<<grid, 256, SMEM_TOTAL>>>(out);
}

// round 6
// speedup vs baseline: 1.8017x; 1.3988x over previous
#include <cuda_runtime.h>
#include <cstdint>

// out[b,n,m] = sum_e A[b,n,e]*B[b,m,e]; b=8, n=m=2048, e=1024, fp32.
// Single-pass TF32 mma.m16n8k8, cp.async direct from fp32 inputs,
// cvt.rna.tf32 in registers. CTA tile 128x256, warp tile 64x64, BK=32.

static constexpr int DN = 2048, DM = 2048, DE = 1024;
static constexpr int BK = 32, NCHUNK = DE / BK;

static constexpr unsigned A_PLANE = 128u * 128u;          // 128 rows x 128B
static constexpr unsigned B_PLANE = 256u * 128u;          // 256 rows x 128B
static constexpr unsigned STAGE   = A_PLANE + B_PLANE;    // 48 KB
static constexpr unsigned SMEM_TOTAL = 2u * STAGE;        // 96 KB

__device__ __forceinline__ unsigned smem_u32(const void* p) {
    unsigned a;
    asm("{ .reg .u64 t; cvta.to.shared.u64 t, %1; cvt.u32.u64 %0, t; }" : "=r"(a) : "l"(p));
    return a;
}

#define LDSM4(r0, r1, r2, r3, addr) \
    asm volatile("ldmatrix.sync.aligned.m8n8.x4.shared.b16 {%0,%1,%2,%3}, [%4];" \
                 : "=r"(r0), "=r"(r1), "=r"(r2), "=r"(r3) : "r"(addr))

#define MMA_TF32(d, a, b) \
    asm volatile("mma.sync.aligned.m16n8k8.row.col.f32.tf32.tf32.f32 " \
                 "{%0,%1,%2,%3},{%4,%5,%6,%7},{%8,%9},{%0,%1,%2,%3};" \
                 : "+f"((d)[0]), "+f"((d)[1]), "+f"((d)[2]), "+f"((d)[3]) \
                 : "r"((a)[0]), "r"((a)[1]), "r"((a)[2]), "r"((a)[3]), \
                   "r"((b)[0]), "r"((b)[1]))

#define CVT_TF32(x) asm volatile("cvt.rna.tf32.f32 %0, %0;" : "+r"(x))

#define CPASYNC16(dst, src) \
    asm volatile("cp.async.cg.shared.global [%0], [%1], 16;" :: "r"(dst), "l"(src))

// One stage: A tile 128 rows, B tile 256 rows; each row = 32 fp32 = 128 B
// contiguous in gmem at this K-chunk. Swizzle: phys idx16 = idx ^ (row & 7).
__device__ __forceinline__ void issue_stage(const float* __restrict__ aT,
                                            const float* __restrict__ bT,
                                            unsigned stg, unsigned tid) {
#pragma unroll
    for (int g = 0; g < 4; ++g) {                  // A: 1024 16-B units
        unsigned u = tid + (unsigned)g * 256u;
        unsigned row = u >> 3, idx = u & 7u;
        unsigned dst = stg + row * 128u + 16u * (idx ^ (row & 7u));
        CPASYNC16(dst, (const void*)(aT + (size_t)row * DE + idx * 4u));
    }
#pragma unroll
    for (int g = 0; g < 8; ++g) {                  // B: 2048 16-B units
        unsigned u = tid + (unsigned)g * 256u;
        unsigned row = u >> 3, idx = u & 7u;
        unsigned dst = stg + A_PLANE + row * 128u + 16u * (idx ^ (row & 7u));
        CPASYNC16(dst, (const void*)(bT + (size_t)row * DE + idx * 4u));
    }
}

__global__ void __launch_bounds__(256, 1)
bmm_tf32_kernel(const float* __restrict__ A, const float* __restrict__ B,
                float* __restrict__ out) {
    extern __shared__ char smem[];
    const unsigned sbase = smem_u32(smem);
    const unsigned tid = threadIdx.x;
    const int wid = (int)(tid >> 5), lane = (int)(tid & 31);
    const int bb = blockIdx.y;
    const int m0 = (int)(blockIdx.x >> 3) * 128;
    const int n0 = (int)(blockIdx.x & 7) * 256;

    const float* aTile = A + ((size_t)(bb * DN + m0)) * DE;
    const float* bTile = B + ((size_t)(bb * DM + n0)) * DE;

    // warp grid 2(M) x 4(N); warp tile 64 x 64
    const int wm = (wid >> 2) * 64, wn = (wid & 3) * 64;
    const int a_r   = lane & 15;
    const int a_sel = (lane >> 4) & 1;
    const int b_r   = (lane & 7) + ((lane >> 4) << 3);
    const int b_sel = (lane >> 3) & 1;

    float acc[4][8][4];
#pragma unroll
    for (int i = 0; i < 4; ++i)
#pragma unroll
        for (int j = 0; j < 8; ++j)
#pragma unroll
            for (int c = 0; c < 4; ++c) acc[i][j][c] = 0.0f;

    issue_stage(aTile, bTile, sbase, tid);
    asm volatile("cp.async.commit_group;" ::: "memory");

    for (int kc = 0; kc < NCHUNK; ++kc) {
        if (kc + 1 < NCHUNK) {
            issue_stage(aTile + (kc + 1) * BK, bTile + (kc + 1) * BK,
                        sbase + (unsigned)((kc + 1) & 1) * STAGE, tid);
            asm volatile("cp.async.commit_group;" ::: "memory");
            asm volatile("cp.async.wait_group 1;" ::: "memory");
        } else {
            asm volatile("cp.async.wait_group 0;" ::: "memory");
        }
        __syncthreads();

        const unsigned stg = sbase + (unsigned)(kc & 1) * STAGE;
        const unsigned sA = stg, sB = stg + A_PLANE;

#pragma unroll
        for (int s = 0; s < 4; ++s) {              // 4 k8 steps per chunk
            unsigned af[4][4], bf[8][2];
            // B fragments: 8 n8 blocks (4 ldmatrix.x4)
#pragma unroll
            for (int jj = 0; jj < 4; ++jj) {
                const unsigned row = (unsigned)(wn + 16 * jj + b_r);
                LDSM4(bf[2*jj][0], bf[2*jj][1], bf[2*jj+1][0], bf[2*jj+1][1],
                      sB + row * 128u + 16u * ((unsigned)(2*s + b_sel) ^ (row & 7u)));
            }
            // A fragments: 4 m16 blocks
#pragma unroll
            for (int i = 0; i < 4; ++i) {
                const unsigned row = (unsigned)(wm + 16 * i + a_r);
                LDSM4(af[i][0], af[i][1], af[i][2], af[i][3],
                      sA + row * 128u + 16u * ((unsigned)(2*s + a_sel) ^ (row & 7u)));
            }
            // round to tf32 (rna) in registers
#pragma unroll
            for (int i = 0; i < 4; ++i) {
                CVT_TF32(af[i][0]); CVT_TF32(af[i][1]);
                CVT_TF32(af[i][2]); CVT_TF32(af[i][3]);
            }
#pragma unroll
            for (int j = 0; j < 8; ++j) { CVT_TF32(bf[j][0]); CVT_TF32(bf[j][1]); }
#pragma unroll
            for (int i = 0; i < 4; ++i)
#pragma unroll
                for (int j = 0; j < 8; ++j)
                    MMA_TF32(acc[i][j], af[i], bf[j]);
        }
        __syncthreads();
    }

    // epilogue: direct float2 global stores
    {
        const int r0 = wm + (lane >> 2);
        const int c0 = wn + 2 * (lane & 3);
        float* obase = out + ((size_t)(bb * DN) + (size_t)m0) * DM + n0;
#pragma unroll
        for (int i = 0; i < 4; ++i)
#pragma unroll
            for (int j = 0; j < 8; ++j) {
                float* p0 = obase + (size_t)(r0 + 16*i) * DM + (c0 + 8*j);
                reinterpret_cast<float2*>(p0)[0] = make_float2(acc[i][j][0], acc[i][j][1]);
                float* p1 = p0 + 8 * DM;
                reinterpret_cast<float2*>(p1)[0] = make_float2(acc[i][j][2], acc[i][j][3]);
            }
    }
}

extern "C" void kernel_launch(void* const* d_in, const int* in_sizes, int n_in,
                              void* d_out, int out_size) {
    const float* A = (const float*)d_in[0];
    const float* B = (const float*)d_in[1];
    float* out = (float*)d_out;
    cudaFuncSetAttribute(bmm_tf32_kernel,
                         cudaFuncAttributeMaxDynamicSharedMemorySize, (int)SMEM_TOTAL);
    dim3 grid(128, 8);   // 16(M) x 8(N) tiles per batch, 8 batches
    bmm_tf32_kernel<<<grid, 256, SMEM_TOTAL>>>(A, B, out);
}